// round 9
// baseline (speedup 1.0000x reference)
#include <cuda_runtime.h>
#include <cstdint>

// Filtering_72773925863700
// out[b,m,n,i] = (F x)_along_m + (F x)_along_n,  F = C C^T (256x32 low-rank,
// C = ortho-normalized cos/sin basis for rfft modes [0,16), exact identity).
// B=8, M=N=256, I=32, fp32.
//
// Round 9: warp-specialized producer + 2-stage mbarrier ring (R8 used 3
// stages and blew the 48KB static-smem limit). Consumers have NO
// __syncthreads in the mainloop; producer issues chunk c+1 as soon as
// consumers drain c-1. 36.9KB smem per kernel.

#define BATCH 8
#define MDIM 256
#define NDIM 256
#define IDIM 32
#define KM 32
#define NI (NDIM * IDIM)   // 8192

__device__ float d_C[MDIM * KM];                   // C[n][k]
__device__ float d_D1[BATCH * KM * NDIM * IDIM];   // [b][k][n][i]
__device__ float d_D2[BATCH * MDIM * KM * IDIM];   // [b][m][k][i]

union F4U { float4 f4; uint64_t u[2]; float f[4]; };
union F2U { float2 f2; uint64_t u; };

__device__ __forceinline__ uint64_t pack2(float c) {
    uint64_t r;
    asm("mov.b64 %0, {%1, %1};" : "=l"(r) : "f"(c));
    return r;
}
__device__ __forceinline__ void fma2(uint64_t& acc, uint64_t a, uint64_t b) {
    asm("fma.rn.f32x2 %0, %1, %2, %0;" : "+l"(acc) : "l"(a), "l"(b));
}
__device__ __forceinline__ uint32_t sm_addr(const void* p) {
    uint32_t a;
    asm("{ .reg .u64 t; cvta.to.shared.u64 t, %1; cvt.u32.u64 %0, t; }"
        : "=r"(a) : "l"(p));
    return a;
}
__device__ __forceinline__ void mbar_init(uint32_t mbar, uint32_t count) {
    asm volatile("mbarrier.init.shared.b64 [%0], %1;" :: "r"(mbar), "r"(count) : "memory");
}
__device__ __forceinline__ void mbar_expect(uint32_t mbar, uint32_t bytes) {
    asm volatile("mbarrier.arrive.expect_tx.shared.b64 _, [%0], %1;"
                 :: "r"(mbar), "r"(bytes) : "memory");
}
__device__ __forceinline__ void mbar_arrive(uint32_t mbar) {
    asm volatile("mbarrier.arrive.shared.b64 _, [%0];" :: "r"(mbar) : "memory");
}
__device__ __forceinline__ void bulk_g2s(uint32_t dst, const void* src,
                                         uint32_t bytes, uint32_t mbar) {
    asm volatile(
        "cp.async.bulk.shared::cta.global.mbarrier::complete_tx::bytes [%0], [%1], %2, [%3];"
        :: "r"(dst), "l"(src), "r"(bytes), "r"(mbar) : "memory");
}
__device__ __forceinline__ void mbar_wait(uint32_t mbar, uint32_t parity) {
    asm volatile(
        "{\n\t"
        ".reg .pred P1;\n\t"
        "WAIT_LOOP_%=:\n\t"
        "mbarrier.try_wait.parity.acquire.cta.shared::cta.b64 P1, [%0], %1;\n\t"
        "@P1 bra.uni WAIT_DONE_%=;\n\t"
        "bra.uni WAIT_LOOP_%=;\n\t"
        "WAIT_DONE_%=:\n\t"
        "}"
        :: "r"(mbar), "r"(parity) : "memory");
}
__device__ __forceinline__ void fence_async() {
    asm volatile("fence.proxy.async.shared::cta;" ::: "memory");
}

// ---------------------------------------------------------------------------
// Init C[n][j]. j=0: 1/16. j=1..15: sqrt2/16*cos(2pi j n/256).
//              j=16..30: sqrt2/16*sin(2pi (j-15) n/256). j=31: 0.
// ---------------------------------------------------------------------------
__global__ void init_C_kernel() {
    int idx = blockIdx.x * 256 + threadIdx.x;   // 8192 total
    int n = idx >> 5;
    int j = idx & 31;
    const double PI = 3.14159265358979323846;
    const double AMP = 1.4142135623730951 / 16.0;
    double v;
    if (j == 0) {
        v = 1.0 / 16.0;
    } else if (j <= 15) {
        int ph = (j * n) & 255;
        v = AMP * cos(2.0 * PI * (double)ph / 256.0);
    } else if (j <= 30) {
        int k = j - 15;
        int ph = (k * n) & 255;
        v = AMP * sin(2.0 * PI * (double)ph / 256.0);
    } else {
        v = 0.0;
    }
    d_C[idx] = (float)v;
}

// ---------------------------------------------------------------------------
// K1: D1[b,k,n,i] = sum_m C[m,k] * x[b,m,n,i]
// Block (jt, b): tile [32k x 256j]. 160 thr = 1 producer warp + 128 consumers.
// Consumer ct: ko=ct>>5 (8 k's), jq=ct&31 (j quads at jq*4 and 128+jq*4).
// 16 chunks of 16 m-rows, 2-stage ring.
// ---------------------------------------------------------------------------
__global__ void __launch_bounds__(160) k1_down_m(const float* __restrict__ x) {
    __shared__ __align__(128) float xs[2][16 * 256];   // 16 KB each
    __shared__ __align__(128) float cs[2][16 * 32];    //  2 KB each
    __shared__ __align__(8) uint64_t full_b[2], empty_b[2];

    int t  = threadIdx.x;
    int b  = blockIdx.y;
    int j0 = blockIdx.x * 256;

    const float* xb = x + (size_t)b * (MDIM * NI);

    if (t == 0) {
#pragma unroll
        for (int s = 0; s < 2; s++) {
            mbar_init(sm_addr(&full_b[s]), 1);
            mbar_init(sm_addr(&empty_b[s]), 128);
        }
    }
    __syncthreads();

    const uint32_t CHUNK_BYTES = 16 * 256 * 4 + 16 * 32 * 4;   // 18432
    const int NCH = 16;

    if (t < 32) {
        // ---- producer warp (thread 0 issues) ----
        if (t == 0) {
            for (int c = 0; c < NCH; c++) {
                int s = c & 1;
                if (c >= 2) {
                    mbar_wait(sm_addr(&empty_b[s]), ((c - 2) >> 1) & 1);
                    fence_async();
                }
                uint32_t fb = sm_addr(&full_b[s]);
                mbar_expect(fb, CHUNK_BYTES);
#pragma unroll
                for (int mm = 0; mm < 16; mm++)
                    bulk_g2s(sm_addr(&xs[s][mm * 256]),
                             &xb[(size_t)(c * 16 + mm) * NI + j0], 1024, fb);
                bulk_g2s(sm_addr(&cs[s][0]), &d_C[c * 16 * 32], 2048, fb);
            }
        }
    } else {
        // ---- consumers ----
        int ct = t - 32;
        int jq = ct & 31;
        int ko = ct >> 5;

        uint64_t acc[8][4];
#pragma unroll
        for (int a = 0; a < 8; a++)
#pragma unroll
            for (int q = 0; q < 4; q++) acc[a][q] = 0ull;

        for (int c = 0; c < NCH; c++) {
            int s = c & 1;
            mbar_wait(sm_addr(&full_b[s]), (c >> 1) & 1);
            const float* xsb = xs[s];
            const float* csb = cs[s];
#pragma unroll
            for (int mm = 0; mm < 16; mm++) {
                F4U x0; x0.f4 = *(const float4*)&xsb[mm * 256 + jq * 4];
                F4U x1; x1.f4 = *(const float4*)&xsb[mm * 256 + 128 + jq * 4];
                F4U c0; c0.f4 = *(const float4*)&csb[mm * 32 + ko * 8];
                F4U c1; c1.f4 = *(const float4*)&csb[mm * 32 + ko * 8 + 4];
                float cv[8] = {c0.f[0], c0.f[1], c0.f[2], c0.f[3],
                               c1.f[0], c1.f[1], c1.f[2], c1.f[3]};
#pragma unroll
                for (int a = 0; a < 8; a++) {
                    uint64_t cp = pack2(cv[a]);
                    fma2(acc[a][0], cp, x0.u[0]);
                    fma2(acc[a][1], cp, x0.u[1]);
                    fma2(acc[a][2], cp, x1.u[0]);
                    fma2(acc[a][3], cp, x1.u[1]);
                }
            }
            mbar_arrive(sm_addr(&empty_b[s]));
        }

#pragma unroll
        for (int a = 0; a < 8; a++) {
            int k = ko * 8 + a;
            F4U v0; v0.u[0] = acc[a][0]; v0.u[1] = acc[a][1];
            F4U v1; v1.u[0] = acc[a][2]; v1.u[1] = acc[a][3];
            *(float4*)&d_D1[((size_t)b * 32 + k) * NI + j0 + jq * 4]       = v0.f4;
            *(float4*)&d_D1[((size_t)b * 32 + k) * NI + j0 + 128 + jq * 4] = v1.f4;
        }
    }
}

// ---------------------------------------------------------------------------
// K2: D2[b,m,k,i] = sum_n C[n,k] * x[b,m,n,i]
// Block (mt of 8 m, b): 288 thr = 1 producer warp + 256 consumers.
// Consumer ct: kq=ct&3 (8 k), iq=(ct>>2)&7 (4 i), ml=ct>>5 (warp-uniform m).
// 16 chunks of 16 n, 2-stage ring.
// ---------------------------------------------------------------------------
__global__ void __launch_bounds__(288) k2_down_n(const float* __restrict__ x) {
    __shared__ __align__(128) float zs[2][8 * 16 * 32];   // 16 KB each
    __shared__ __align__(128) float ch[2][16 * 32];       //  2 KB each
    __shared__ __align__(8) uint64_t full_b[2], empty_b[2];

    int t  = threadIdx.x;
    int b  = blockIdx.y;
    int m0 = blockIdx.x * 8;

    const float* xb = x + (size_t)b * (MDIM * NI) + (size_t)m0 * NI;

    if (t == 0) {
#pragma unroll
        for (int s = 0; s < 2; s++) {
            mbar_init(sm_addr(&full_b[s]), 1);
            mbar_init(sm_addr(&empty_b[s]), 256);
        }
    }
    __syncthreads();

    const uint32_t CHUNK_BYTES = 8 * 16 * 32 * 4 + 16 * 32 * 4;   // 18432
    const int NCH = 16;

    if (t < 32) {
        if (t == 0) {
            for (int c = 0; c < NCH; c++) {
                int s = c & 1;
                if (c >= 2) {
                    mbar_wait(sm_addr(&empty_b[s]), ((c - 2) >> 1) & 1);
                    fence_async();
                }
                uint32_t fb = sm_addr(&full_b[s]);
                mbar_expect(fb, CHUNK_BYTES);
#pragma unroll
                for (int m2 = 0; m2 < 8; m2++)
                    bulk_g2s(sm_addr(&zs[s][m2 * 16 * 32]),
                             &xb[(size_t)m2 * NI + c * 16 * 32], 2048, fb);
                bulk_g2s(sm_addr(&ch[s][0]), &d_C[c * 16 * 32], 2048, fb);
            }
        }
    } else {
        int ct = t - 32;
        int kq = ct & 3;
        int iq = (ct >> 2) & 7;
        int ml = ct >> 5;   // 0..7, warp-uniform

        uint64_t acc[8][2];
#pragma unroll
        for (int kk = 0; kk < 8; kk++) { acc[kk][0] = 0ull; acc[kk][1] = 0ull; }

        for (int c = 0; c < NCH; c++) {
            int s = c & 1;
            mbar_wait(sm_addr(&full_b[s]), (c >> 1) & 1);
            const float* zb = zs[s];
            const float* cb = ch[s];
#pragma unroll
            for (int nn = 0; nn < 16; nn++) {
                F4U z; z.f4 = *(const float4*)&zb[(ml * 16 + nn) * 32 + iq * 4];
                F4U c0; c0.f4 = *(const float4*)&cb[nn * 32 + kq * 8];
                F4U c1; c1.f4 = *(const float4*)&cb[nn * 32 + kq * 8 + 4];
                float cv[8] = {c0.f[0], c0.f[1], c0.f[2], c0.f[3],
                               c1.f[0], c1.f[1], c1.f[2], c1.f[3]};
#pragma unroll
                for (int kk = 0; kk < 8; kk++) {
                    uint64_t cp = pack2(cv[kk]);
                    fma2(acc[kk][0], cp, z.u[0]);
                    fma2(acc[kk][1], cp, z.u[1]);
                }
            }
            mbar_arrive(sm_addr(&empty_b[s]));
        }

#pragma unroll
        for (int kk = 0; kk < 8; kk++) {
            int k = kq * 8 + kk;
            F4U v; v.u[0] = acc[kk][0]; v.u[1] = acc[kk][1];
            *(float4*)&d_D2[(((size_t)b * MDIM + m0 + ml) * 32 + k) * 32 + iq * 4] = v.f4;
        }
    }
}

// ---------------------------------------------------------------------------
// K3: out[b,m,n,i] = sum_k C[m,k]*D1[b,k,n,i] + sum_k C[n,k]*D2[b,m,k,i]
// Block (mt, nt, b): 16m x 16n x 32i tile. 160 thr = producer + 128 consumers.
// Consumer ct: io=ct&15 (2 i), nq=(ct>>4)&3 (4 n), mp=ct>>6 (8 m, warp-unif).
// 8 chunks of 4 k, 2-stage ring.
// ---------------------------------------------------------------------------
__global__ void __launch_bounds__(160) k3_up(float* __restrict__ out) {
    __shared__ __align__(128) float d1s[2][4 * 16 * 32];   // 8 KB each
    __shared__ __align__(128) float d2s[2][16 * 4 * 32];   // 8 KB each
    __shared__ __align__(16) float cms2[32 * 16];          // [k][mm]
    __shared__ __align__(16) float cns2[32 * 16];          // [k][nn]
    __shared__ __align__(8) uint64_t full_b[2], empty_b[2];

    int t  = threadIdx.x;
    int mt = blockIdx.x;
    int nt = blockIdx.y;
    int b  = blockIdx.z;

    if (t == 0) {
#pragma unroll
        for (int s = 0; s < 2; s++) {
            mbar_init(sm_addr(&full_b[s]), 1);
            mbar_init(sm_addr(&empty_b[s]), 128);
        }
    }
    // Stage transposed C tiles (512 each) with all 160 threads.
    for (int idx = t; idx < 512; idx += 160) {
        int k  = idx >> 4;
        int mm = idx & 15;
        cms2[idx] = d_C[(mt * 16 + mm) * 32 + k];
        cns2[idx] = d_C[(nt * 16 + mm) * 32 + k];
    }
    __syncthreads();

    const uint32_t CHUNK_BYTES = 2 * 4 * 16 * 32 * 4;   // 16384
    const int NCH = 8;

    if (t < 32) {
        if (t == 0) {
            for (int c = 0; c < NCH; c++) {
                int s = c & 1;
                if (c >= 2) {
                    mbar_wait(sm_addr(&empty_b[s]), ((c - 2) >> 1) & 1);
                    fence_async();
                }
                uint32_t fb = sm_addr(&full_b[s]);
                mbar_expect(fb, CHUNK_BYTES);
#pragma unroll
                for (int kk = 0; kk < 4; kk++)
                    bulk_g2s(sm_addr(&d1s[s][kk * 512]),
                             &d_D1[((size_t)b * 32 + c * 4 + kk) * NI + nt * 512],
                             2048, fb);
#pragma unroll
                for (int mm = 0; mm < 16; mm++)
                    bulk_g2s(sm_addr(&d2s[s][mm * 128]),
                             &d_D2[(((size_t)b * MDIM + mt * 16 + mm) * 32 + c * 4) * 32],
                             512, fb);
            }
        }
    } else {
        int ct = t - 32;
        int io = ct & 15;
        int nq = (ct >> 4) & 3;
        int mp = ct >> 6;

        uint64_t acc[8][4];
#pragma unroll
        for (int j = 0; j < 8; j++)
#pragma unroll
            for (int a = 0; a < 4; a++) acc[j][a] = 0ull;

        for (int c = 0; c < NCH; c++) {
            int s = c & 1;
            mbar_wait(sm_addr(&full_b[s]), (c >> 1) & 1);
            const float* d1b = d1s[s];
            const float* d2b = d2s[s];

#pragma unroll
            for (int kk = 0; kk < 4; kk++) {
                int k = c * 4 + kk;

                F4U cmA, cmB, cnv;
                cmA.f4 = *(const float4*)&cms2[k * 16 + mp * 8];
                cmB.f4 = *(const float4*)&cms2[k * 16 + mp * 8 + 4];
                cnv.f4 = *(const float4*)&cns2[k * 16 + nq * 4];

                uint64_t cnp[4];
#pragma unroll
                for (int a = 0; a < 4; a++) cnp[a] = pack2(cnv.f[a]);

                F2U d1v[4], d2v[8];
#pragma unroll
                for (int a = 0; a < 4; a++)
                    d1v[a].f2 = *(const float2*)&d1b[(kk * 16 + nq * 4 + a) * 32 + io * 2];
#pragma unroll
                for (int j = 0; j < 8; j++)
                    d2v[j].f2 = *(const float2*)&d2b[((mp * 8 + j) * 4 + kk) * 32 + io * 2];

                float cmf[8] = {cmA.f[0], cmA.f[1], cmA.f[2], cmA.f[3],
                                cmB.f[0], cmB.f[1], cmB.f[2], cmB.f[3]};
#pragma unroll
                for (int j = 0; j < 8; j++) {
                    uint64_t cmp = pack2(cmf[j]);
#pragma unroll
                    for (int a = 0; a < 4; a++) {
                        fma2(acc[j][a], cmp, d1v[a].u);
                        fma2(acc[j][a], cnp[a], d2v[j].u);
                    }
                }
            }
            mbar_arrive(sm_addr(&empty_b[s]));
        }

#pragma unroll
        for (int j = 0; j < 8; j++) {
            int m = mt * 16 + mp * 8 + j;
#pragma unroll
            for (int a = 0; a < 4; a++) {
                int n = nt * 16 + nq * 4 + a;
                F2U v; v.u = acc[j][a];
                *(float2*)&out[((size_t)b * MDIM + m) * NI + n * 32 + io * 2] = v.f2;
            }
        }
    }
}

// ---------------------------------------------------------------------------
extern "C" void kernel_launch(void* const* d_in, const int* in_sizes, int n_in,
                              void* d_out, int out_size) {
    const float* x = (const float*)d_in[0];
    float* out = (float*)d_out;

    init_C_kernel<<<32, 256>>>();
    k1_down_m<<<dim3(32, 8), 160>>>(x);
    k2_down_n<<<dim3(32, 8), 288>>>(x);
    k3_up<<<dim3(16, 16, 8), 160>>>(out);
}